// round 8
// baseline (speedup 1.0000x reference)
#include <cuda_runtime.h>
#include <cuda_bf16.h>
#include <cstdint>

#define N_NODES_MAX 100000
#define E_MAX       1600000
#define FDIM        128
#define SCAN_B      1024
#define NCHUNK      8

// ---------------- scratch (device globals; no allocations allowed) ----------
__device__ float g_h[N_NODES_MAX * FDIM];    // ping buffer
__device__ float g_h2[N_NODES_MAX * FDIM];   // pong buffer
__device__ float g_buf[N_NODES_MAX * FDIM];  // gather output
__device__ float g_dis[N_NODES_MAX];
__device__ int   g_cnt[N_NODES_MAX];
__device__ int   g_rowptr[N_NODES_MAX];
__device__ int   g_cursor[N_NODES_MAX];
__device__ int   g_bsum[(N_NODES_MAX + SCAN_B - 1) / SCAN_B + 1];
__device__ int   g_csr_src[E_MAX];
__device__ float g_csr_norm[E_MAX];

// ---------------- CSR build --------------------------------------------------
__global__ void zero_cnt_kernel(int* cnt, int n) {
    int i = blockIdx.x * blockDim.x + threadIdx.x;
    if (i < n) cnt[i] = 0;
}

__global__ void hist_kernel(const int* __restrict__ dst, int* cnt, int E) {
    int e = blockIdx.x * blockDim.x + threadIdx.x;
    if (e < E) atomicAdd(&cnt[dst[e]], 1);
}

__global__ void dis_kernel(const int* __restrict__ cnt, float* dis, int n) {
    int i = blockIdx.x * blockDim.x + threadIdx.x;
    if (i < n) dis[i] = rsqrtf((float)(cnt[i] + 1));
}

__global__ void scan1_kernel(const int* __restrict__ cnt, int* rowptr, int* bsum, int n) {
    __shared__ int sh[SCAN_B];
    int gid = blockIdx.x * SCAN_B + threadIdx.x;
    int v = (gid < n) ? cnt[gid] : 0;
    sh[threadIdx.x] = v;
    __syncthreads();
#pragma unroll
    for (int off = 1; off < SCAN_B; off <<= 1) {
        int t = (threadIdx.x >= off) ? sh[threadIdx.x - off] : 0;
        __syncthreads();
        sh[threadIdx.x] += t;
        __syncthreads();
    }
    if (gid < n) rowptr[gid] = sh[threadIdx.x] - v;
    if (threadIdx.x == SCAN_B - 1) bsum[blockIdx.x] = sh[SCAN_B - 1];
}

__global__ void scan2_kernel(int* bsum, int nb) {
    __shared__ int sh[SCAN_B];
    int v = (threadIdx.x < nb) ? bsum[threadIdx.x] : 0;
    sh[threadIdx.x] = v;
    __syncthreads();
#pragma unroll
    for (int off = 1; off < SCAN_B; off <<= 1) {
        int t = (threadIdx.x >= off) ? sh[threadIdx.x - off] : 0;
        __syncthreads();
        sh[threadIdx.x] += t;
        __syncthreads();
    }
    if (threadIdx.x < nb) bsum[threadIdx.x] = sh[threadIdx.x] - v;
}

__global__ void scan3_kernel(int* rowptr, int* cursor, const int* __restrict__ bsum, int n) {
    int gid = blockIdx.x * blockDim.x + threadIdx.x;
    if (gid < n) {
        int r = rowptr[gid] + bsum[gid / SCAN_B];
        rowptr[gid] = r;
        cursor[gid] = r;
    }
}

__global__ void permute_kernel(const int* __restrict__ src, const int* __restrict__ dst,
                               const float* __restrict__ dis, int* cursor,
                               int* csr_src, float* csr_norm, int E) {
    int e = blockIdx.x * blockDim.x + threadIdx.x;
    if (e < E) {
        int s = src[e], d = dst[e];
        int pos = atomicAdd(&cursor[d], 1);
        csr_src[pos] = s;
        csr_norm[pos] = dis[s] * dis[d];
    }
}

// ---------------- tensor-core GEMM (bf16x2 split, mma.sync) -----------------
__device__ __forceinline__ uint32_t pack_bf16x2(__nv_bfloat16 e0, __nv_bfloat16 e1) {
    return ((uint32_t)__bfloat16_as_ushort(e1) << 16) | (uint32_t)__bfloat16_as_ushort(e0);
}

__device__ __forceinline__ void split_store4(float4 v, __nv_bfloat16* ph, __nv_bfloat16* pl) {
    __nv_bfloat16 h0 = __float2bfloat16(v.x);
    __nv_bfloat16 h1 = __float2bfloat16(v.y);
    __nv_bfloat16 h2 = __float2bfloat16(v.z);
    __nv_bfloat16 h3 = __float2bfloat16(v.w);
    __nv_bfloat16 l0 = __float2bfloat16(v.x - __bfloat162float(h0));
    __nv_bfloat16 l1 = __float2bfloat16(v.y - __bfloat162float(h1));
    __nv_bfloat16 l2 = __float2bfloat16(v.z - __bfloat162float(h2));
    __nv_bfloat16 l3 = __float2bfloat16(v.w - __bfloat162float(h3));
    uint2 uh = make_uint2(pack_bf16x2(h0, h1), pack_bf16x2(h2, h3));
    uint2 ul = make_uint2(pack_bf16x2(l0, l1), pack_bf16x2(l2, l3));
    *reinterpret_cast<uint2*>(ph) = uh;
    *reinterpret_cast<uint2*>(pl) = ul;
}

#define MMA_BF16(acc, a, b)                                                              \
    asm volatile(                                                                        \
        "mma.sync.aligned.m16n8k16.row.col.f32.bf16.bf16.f32 "                           \
        "{%0,%1,%2,%3}, {%4,%5,%6,%7}, {%8,%9}, {%0,%1,%2,%3};"                          \
        : "+f"((acc)[0]), "+f"((acc)[1]), "+f"((acc)[2]), "+f"((acc)[3])                 \
        : "r"((a)[0]), "r"((a)[1]), "r"((a)[2]), "r"((a)[3]), "r"((b)[0]), "r"((b)[1]))

template <int BN, bool RELU>
__global__ __launch_bounds__(256) void gemm_tc_kernel(const float* __restrict__ A,
                                                      const float* __restrict__ W,
                                                      float* __restrict__ out, int M) {
    constexpr int K = 128;
    constexpr int NWN = BN / 32;
    constexpr int NWM = 8 / NWN;
    constexpr int BM = NWM * 32;
    constexpr int KP = K + 8;
    constexpr int NP = BN + 8;

    extern __shared__ __nv_bfloat16 smb[];
    __nv_bfloat16* Ah = smb;
    __nv_bfloat16* Al = Ah + BM * KP;
    __nv_bfloat16* Wh = Al + BM * KP;
    __nv_bfloat16* Wl = Wh + K * NP;

    const int t = threadIdx.x;
    const int block_row = blockIdx.x * BM;

    for (int i = t * 4; i < K * BN; i += 1024) {
        const int k = i / BN, n = i % BN;
        float4 v = *reinterpret_cast<const float4*>(W + i);
        split_store4(v, Wh + k * NP + n, Wl + k * NP + n);
    }
    for (int i = t * 4; i < BM * K; i += 1024) {
        const int r = i >> 7, c = i & 127;
        const int row = block_row + r;
        float4 v = make_float4(0.f, 0.f, 0.f, 0.f);
        if (row < M) v = *reinterpret_cast<const float4*>(A + (size_t)row * K + c);
        if (RELU) {
            v.x = fmaxf(v.x, 0.f); v.y = fmaxf(v.y, 0.f);
            v.z = fmaxf(v.z, 0.f); v.w = fmaxf(v.w, 0.f);
        }
        split_store4(v, Ah + r * KP + c, Al + r * KP + c);
    }
    __syncthreads();

    const int w = t >> 5, l = t & 31;
    const int wm = w / NWN, wn = w % NWN;
    const int g = l >> 2, tq = l & 3;

    float acc[2][4][4];
#pragma unroll
    for (int mi = 0; mi < 2; mi++)
#pragma unroll
        for (int ni = 0; ni < 4; ni++)
#pragma unroll
            for (int r = 0; r < 4; r++) acc[mi][ni][r] = 0.f;

    const int a_row0 = wm * 32 + g;
    const int b_row  = l & 15;
    const int b_col  = wn * 32;

#pragma unroll
    for (int kk = 0; kk < 8; kk++) {
        const int k0 = kk * 16;
        uint32_t ah[2][4], al_[2][4];
#pragma unroll
        for (int mi = 0; mi < 2; mi++) {
            const int rb = (a_row0 + mi * 16) * KP + k0 + 2 * tq;
            ah[mi][0]  = *reinterpret_cast<const uint32_t*>(Ah + rb);
            ah[mi][1]  = *reinterpret_cast<const uint32_t*>(Ah + rb + 8 * KP);
            ah[mi][2]  = *reinterpret_cast<const uint32_t*>(Ah + rb + 8);
            ah[mi][3]  = *reinterpret_cast<const uint32_t*>(Ah + rb + 8 * KP + 8);
            al_[mi][0] = *reinterpret_cast<const uint32_t*>(Al + rb);
            al_[mi][1] = *reinterpret_cast<const uint32_t*>(Al + rb + 8 * KP);
            al_[mi][2] = *reinterpret_cast<const uint32_t*>(Al + rb + 8);
            al_[mi][3] = *reinterpret_cast<const uint32_t*>(Al + rb + 8 * KP + 8);
        }
        uint32_t bh[4][2], bl[4][2];
#pragma unroll
        for (int ni = 0; ni < 4; ni++) {
            const int off = (k0 + b_row) * NP + b_col + ni * 8;
            uint32_t ph = (uint32_t)__cvta_generic_to_shared(Wh + off);
            uint32_t pl = (uint32_t)__cvta_generic_to_shared(Wl + off);
            asm volatile("ldmatrix.sync.aligned.m8n8.x2.trans.shared.b16 {%0,%1}, [%2];"
                         : "=r"(bh[ni][0]), "=r"(bh[ni][1]) : "r"(ph));
            asm volatile("ldmatrix.sync.aligned.m8n8.x2.trans.shared.b16 {%0,%1}, [%2];"
                         : "=r"(bl[ni][0]), "=r"(bl[ni][1]) : "r"(pl));
        }
#pragma unroll
        for (int mi = 0; mi < 2; mi++)
#pragma unroll
            for (int ni = 0; ni < 4; ni++) {
                MMA_BF16(acc[mi][ni], ah[mi], bh[ni]);
                MMA_BF16(acc[mi][ni], ah[mi], bl[ni]);
                MMA_BF16(acc[mi][ni], al_[mi], bh[ni]);
            }
    }

#pragma unroll
    for (int mi = 0; mi < 2; mi++) {
#pragma unroll
        for (int ni = 0; ni < 4; ni++) {
            const int row = block_row + wm * 32 + mi * 16 + g;
            const int col = wn * 32 + ni * 8 + 2 * tq;
            if (row < M)
                *reinterpret_cast<float2*>(out + (size_t)row * BN + col) =
                    make_float2(acc[mi][ni][0], acc[mi][ni][1]);
            if (row + 8 < M)
                *reinterpret_cast<float2*>(out + (size_t)(row + 8) * BN + col) =
                    make_float2(acc[mi][ni][2], acc[mi][ni][3]);
        }
    }
}

// ---------------- aggregation: warp-per-node CSR gather ---------------------
__device__ __forceinline__ void stcs4(float* p, float4 v) {
    asm volatile("st.global.cs.v4.f32 [%0], {%1,%2,%3,%4};"
                 :: "l"(p), "f"(v.x), "f"(v.y), "f"(v.z), "f"(v.w) : "memory");
}

// nodes [v0, v1)
__global__ void agg_gather128_kernel(const float* __restrict__ h,
                                     const int* __restrict__ rowptr,
                                     const int* __restrict__ cnt,
                                     const int* __restrict__ csr_src,
                                     const float* __restrict__ csr_norm,
                                     const float* __restrict__ b,
                                     const float* __restrict__ dis,
                                     float* __restrict__ out, int v0, int v1) {
    int v = v0 + ((blockIdx.x * blockDim.x + threadIdx.x) >> 5);
    int lane = threadIdx.x & 31;
    if (v >= v1) return;
    const int c = lane * 4;

    float d = dis[v];
    float sn = d * d;
    float4 acc = *reinterpret_cast<const float4*>(b + c);
    float4 hv = *reinterpret_cast<const float4*>(h + (size_t)v * 128 + c);
    acc.x += sn * hv.x; acc.y += sn * hv.y; acc.z += sn * hv.z; acc.w += sn * hv.w;

    int j = rowptr[v];
    const int end = j + cnt[v];
    for (; j + 8 <= end; j += 8) {
        int s[8]; float nn[8];
#pragma unroll
        for (int q = 0; q < 8; q++) { s[q] = __ldg(csr_src + j + q); nn[q] = __ldg(csr_norm + j + q); }
        float4 vv[8];
#pragma unroll
        for (int q = 0; q < 8; q++)
            vv[q] = *reinterpret_cast<const float4*>(h + (size_t)s[q] * 128 + c);
#pragma unroll
        for (int q = 0; q < 8; q++) {
            acc.x += nn[q] * vv[q].x; acc.y += nn[q] * vv[q].y;
            acc.z += nn[q] * vv[q].z; acc.w += nn[q] * vv[q].w;
        }
    }
    for (; j < end; ++j) {
        int s = __ldg(csr_src + j);
        float nn = __ldg(csr_norm + j);
        float4 vv = *reinterpret_cast<const float4*>(h + (size_t)s * 128 + c);
        acc.x += nn * vv.x; acc.y += nn * vv.y; acc.z += nn * vv.z; acc.w += nn * vv.w;
    }
    stcs4(out + (size_t)v * 128 + c, acc);
}

// final layer: 64-dim gather fused with relu + log_softmax -> d_out
__global__ void agg_final_kernel(const float* __restrict__ h,
                                 const int* __restrict__ rowptr,
                                 const int* __restrict__ cnt,
                                 const int* __restrict__ csr_src,
                                 const float* __restrict__ csr_norm,
                                 const float* __restrict__ b,
                                 const float* __restrict__ dis,
                                 float* __restrict__ out, int n) {
    int v = (blockIdx.x * blockDim.x + threadIdx.x) >> 5;
    int lane = threadIdx.x & 31;
    if (v >= n) return;
    const int c = lane * 2;

    float d = dis[v];
    float sn = d * d;
    float2 acc = *reinterpret_cast<const float2*>(b + c);
    float2 hv = *reinterpret_cast<const float2*>(h + (size_t)v * 64 + c);
    acc.x += sn * hv.x; acc.y += sn * hv.y;

    int j = rowptr[v];
    const int end = j + cnt[v];
    for (; j + 8 <= end; j += 8) {
        int s[8]; float nn[8];
#pragma unroll
        for (int q = 0; q < 8; q++) { s[q] = __ldg(csr_src + j + q); nn[q] = __ldg(csr_norm + j + q); }
        float2 vv[8];
#pragma unroll
        for (int q = 0; q < 8; q++)
            vv[q] = *reinterpret_cast<const float2*>(h + (size_t)s[q] * 64 + c);
#pragma unroll
        for (int q = 0; q < 8; q++) { acc.x += nn[q] * vv[q].x; acc.y += nn[q] * vv[q].y; }
    }
    for (; j < end; ++j) {
        int s = __ldg(csr_src + j);
        float nn = __ldg(csr_norm + j);
        float2 vv = *reinterpret_cast<const float2*>(h + (size_t)s * 64 + c);
        acc.x += nn * vv.x; acc.y += nn * vv.y;
    }

    // relu + log_softmax over the 64 values held by this warp
    float r0 = fmaxf(acc.x, 0.f);
    float r1 = fmaxf(acc.y, 0.f);
    float m = fmaxf(r0, r1);
#pragma unroll
    for (int o = 16; o > 0; o >>= 1) m = fmaxf(m, __shfl_xor_sync(0xffffffffu, m, o));
    float s = __expf(r0 - m) + __expf(r1 - m);
#pragma unroll
    for (int o = 16; o > 0; o >>= 1) s += __shfl_xor_sync(0xffffffffu, s, o);
    float lg = m + __logf(s);
    float2 res = make_float2(r0 - lg, r1 - lg);
    *reinterpret_cast<float2*>(out + (size_t)v * 64 + c) = res;
}

// ---------------- launch ----------------------------------------------------
extern "C" void kernel_launch(void* const* d_in, const int* in_sizes, int n_in,
                              void* d_out, int out_size) {
    const float* x  = (const float*)d_in[0];
    const int*   ei = (const int*)d_in[1];
    const float* W0 = (const float*)d_in[2];
    const float* b0 = (const float*)d_in[3];
    const float* W1 = (const float*)d_in[4];
    const float* b1 = (const float*)d_in[5];
    const float* W2 = (const float*)d_in[6];
    const float* b2 = (const float*)d_in[7];

    const int N = in_sizes[0] / FDIM;
    const int E = in_sizes[1] / 2;
    const int* src = ei;
    const int* dst = ei + E;

    float *hA, *hB, *buf, *dis, *csr_norm;
    int *cnt, *rowptr, *cursor, *bsum, *csr_src;
    cudaGetSymbolAddress((void**)&hA, g_h);
    cudaGetSymbolAddress((void**)&hB, g_h2);
    cudaGetSymbolAddress((void**)&buf, g_buf);
    cudaGetSymbolAddress((void**)&dis, g_dis);
    cudaGetSymbolAddress((void**)&cnt, g_cnt);
    cudaGetSymbolAddress((void**)&rowptr, g_rowptr);
    cudaGetSymbolAddress((void**)&cursor, g_cursor);
    cudaGetSymbolAddress((void**)&bsum, g_bsum);
    cudaGetSymbolAddress((void**)&csr_src, g_csr_src);
    cudaGetSymbolAddress((void**)&csr_norm, g_csr_norm);

    const int smemTC128 = (2 * 64 * 136 + 2 * 128 * 136) * 2;   // 104448
    const int smemTC64  = (2 * 128 * 136 + 2 * 128 * 72) * 2;   // 106496
    cudaFuncSetAttribute((const void*)gemm_tc_kernel<128, false>,
                         cudaFuncAttributeMaxDynamicSharedMemorySize, smemTC128);
    cudaFuncSetAttribute((const void*)gemm_tc_kernel<128, true>,
                         cudaFuncAttributeMaxDynamicSharedMemorySize, smemTC128);
    cudaFuncSetAttribute((const void*)gemm_tc_kernel<64, true>,
                         cudaFuncAttributeMaxDynamicSharedMemorySize, smemTC64);

    // side stream + event pool, created once on the (uncaptured) correctness call
    static cudaStream_t s2 = nullptr;
    static cudaEvent_t evFork = nullptr, evJoin = nullptr;
    static cudaEvent_t evG[2][NCHUNK + 1];   // gather-chunk done
    static cudaEvent_t evM[2];               // all gemm chunks done
    if (s2 == nullptr) {
        cudaStreamCreate(&s2);
        cudaEventCreateWithFlags(&evFork, cudaEventDisableTiming);
        cudaEventCreateWithFlags(&evJoin, cudaEventDisableTiming);
        for (int l = 0; l < 2; l++) {
            cudaEventCreateWithFlags(&evM[l], cudaEventDisableTiming);
            for (int c = 0; c <= NCHUNK; c++)
                cudaEventCreateWithFlags(&evG[l][c], cudaEventDisableTiming);
        }
    }

    const int T = 256;
    auto cdiv = [](long long a, long long b) { return (unsigned)((a + b - 1) / b); };
    const int nb = (int)cdiv(N, SCAN_B);

    // chunking (multiple of 64 for GEMM tiles)
    const int CHUNK = (int)((cdiv(N, NCHUNK) + 63) / 64) * 64;
    const int nch = (int)cdiv(N, CHUNK);

    // ---- fork: CSR build on s2, GEMM-0 on main ----
    cudaEventRecord(evFork, 0);
    cudaStreamWaitEvent(s2, evFork, 0);

    zero_cnt_kernel<<<cdiv(N, T), T, 0, s2>>>(cnt, N);
    hist_kernel<<<cdiv(E, T), T, 0, s2>>>(dst, cnt, E);
    dis_kernel<<<cdiv(N, T), T, 0, s2>>>(cnt, dis, N);
    scan1_kernel<<<nb, SCAN_B, 0, s2>>>(cnt, rowptr, bsum, N);
    scan2_kernel<<<1, SCAN_B, 0, s2>>>(bsum, nb);
    scan3_kernel<<<cdiv(N, T), T, 0, s2>>>(rowptr, cursor, bsum, N);
    permute_kernel<<<cdiv(E, T), T, 0, s2>>>(src, dst, dis, cursor, csr_src, csr_norm, E);
    cudaEventRecord(evJoin, s2);

    gemm_tc_kernel<128, false><<<cdiv(N, 64), T, smemTC128>>>(x, W0, hA, N);

    cudaStreamWaitEvent(0, evJoin, 0);  // gathers need CSR

    // ---- layer 0 gather (hA -> buf) pipelined with layer 1 GEMM (buf -> hB) ----
    for (int c = 0; c < nch; c++) {
        const int off = c * CHUNK;
        const int sz = (off + CHUNK <= N) ? CHUNK : (N - off);
        agg_gather128_kernel<<<cdiv((long long)sz * 32, T), T>>>(
            hA, rowptr, cnt, csr_src, csr_norm, b0, dis, buf, off, off + sz);
        cudaEventRecord(evG[0][c], 0);
        cudaStreamWaitEvent(s2, evG[0][c], 0);
        gemm_tc_kernel<128, true><<<cdiv(sz, 64), T, smemTC128, s2>>>(
            buf + (size_t)off * 128, W1, hB + (size_t)off * 128, sz);
    }
    cudaEventRecord(evM[0], s2);
    cudaStreamWaitEvent(0, evM[0], 0);  // layer-1 gather needs all of hB

    // ---- layer 1 gather (hB -> buf) pipelined with layer 2 GEMM (buf -> hA) ----
    for (int c = 0; c < nch; c++) {
        const int off = c * CHUNK;
        const int sz = (off + CHUNK <= N) ? CHUNK : (N - off);
        agg_gather128_kernel<<<cdiv((long long)sz * 32, T), T>>>(
            hB, rowptr, cnt, csr_src, csr_norm, b1, dis, buf, off, off + sz);
        cudaEventRecord(evG[1][c], 0);
        cudaStreamWaitEvent(s2, evG[1][c], 0);
        gemm_tc_kernel<64, true><<<cdiv(sz, 128), T, smemTC64, s2>>>(
            buf + (size_t)off * 128, W2, hA + (size_t)off * 64, sz);
    }
    cudaEventRecord(evM[1], s2);
    cudaStreamWaitEvent(0, evM[1], 0);  // final gather needs all of hA

    // ---- final: 64-dim gather + relu + log_softmax fused -> d_out ----
    agg_final_kernel<<<cdiv((long long)N * 32, T), T>>>(
        hA, rowptr, cnt, csr_src, csr_norm, b2, dis, (float*)d_out, N);
}

// round 10
// speedup vs baseline: 1.1931x; 1.1931x over previous
#include <cuda_runtime.h>
#include <cuda_bf16.h>
#include <cuda_fp16.h>
#include <cstdint>

#define N_NODES_MAX 100000
#define E_MAX       1600000
#define FDIM        128
#define SCAN_B      1024

// ---------------- scratch (device globals; no allocations allowed) ----------
__device__ __half g_h[N_NODES_MAX * FDIM];   // GEMM output, fp16 (25.6 MB)
__device__ float  g_buf[N_NODES_MAX * FDIM]; // gather output, fp32 (51.2 MB)
__device__ float  g_dis[N_NODES_MAX];
__device__ int    g_cnt[N_NODES_MAX];
__device__ int    g_rowptr[N_NODES_MAX];
__device__ int    g_cursor[N_NODES_MAX];
__device__ int    g_bsum[(N_NODES_MAX + SCAN_B - 1) / SCAN_B + 1];
__device__ int    g_csr_src[E_MAX];
__device__ float  g_csr_norm[E_MAX];

// ---------------- CSR build --------------------------------------------------
__global__ void zero_cnt_kernel(int* cnt, int n) {
    int i = blockIdx.x * blockDim.x + threadIdx.x;
    if (i < n) cnt[i] = 0;
}

__global__ void hist_kernel(const int* __restrict__ dst, int* cnt, int E) {
    int e = blockIdx.x * blockDim.x + threadIdx.x;
    if (e < E) atomicAdd(&cnt[dst[e]], 1);
}

__global__ void dis_kernel(const int* __restrict__ cnt, float* dis, int n) {
    int i = blockIdx.x * blockDim.x + threadIdx.x;
    if (i < n) dis[i] = rsqrtf((float)(cnt[i] + 1));
}

__global__ void scan1_kernel(const int* __restrict__ cnt, int* rowptr, int* bsum, int n) {
    __shared__ int sh[SCAN_B];
    int gid = blockIdx.x * SCAN_B + threadIdx.x;
    int v = (gid < n) ? cnt[gid] : 0;
    sh[threadIdx.x] = v;
    __syncthreads();
#pragma unroll
    for (int off = 1; off < SCAN_B; off <<= 1) {
        int t = (threadIdx.x >= off) ? sh[threadIdx.x - off] : 0;
        __syncthreads();
        sh[threadIdx.x] += t;
        __syncthreads();
    }
    if (gid < n) rowptr[gid] = sh[threadIdx.x] - v;
    if (threadIdx.x == SCAN_B - 1) bsum[blockIdx.x] = sh[SCAN_B - 1];
}

__global__ void scan2_kernel(int* bsum, int nb) {
    __shared__ int sh[SCAN_B];
    int v = (threadIdx.x < nb) ? bsum[threadIdx.x] : 0;
    sh[threadIdx.x] = v;
    __syncthreads();
#pragma unroll
    for (int off = 1; off < SCAN_B; off <<= 1) {
        int t = (threadIdx.x >= off) ? sh[threadIdx.x - off] : 0;
        __syncthreads();
        sh[threadIdx.x] += t;
        __syncthreads();
    }
    if (threadIdx.x < nb) bsum[threadIdx.x] = sh[threadIdx.x] - v;
}

__global__ void scan3_kernel(int* rowptr, int* cursor, const int* __restrict__ bsum, int n) {
    int gid = blockIdx.x * blockDim.x + threadIdx.x;
    if (gid < n) {
        int r = rowptr[gid] + bsum[gid / SCAN_B];
        rowptr[gid] = r;
        cursor[gid] = r;
    }
}

__global__ void permute_kernel(const int* __restrict__ src, const int* __restrict__ dst,
                               const float* __restrict__ dis, int* cursor,
                               int* csr_src, float* csr_norm, int E) {
    int e = blockIdx.x * blockDim.x + threadIdx.x;
    if (e < E) {
        int s = src[e], d = dst[e];
        int pos = atomicAdd(&cursor[d], 1);
        csr_src[pos] = s;
        csr_norm[pos] = dis[s] * dis[d];
    }
}

// ---------------- tensor-core GEMM (bf16x2 split, mma.sync), fp16 output ----
__device__ __forceinline__ uint32_t pack_bf16x2(__nv_bfloat16 e0, __nv_bfloat16 e1) {
    return ((uint32_t)__bfloat16_as_ushort(e1) << 16) | (uint32_t)__bfloat16_as_ushort(e0);
}

__device__ __forceinline__ void split_store4(float4 v, __nv_bfloat16* ph, __nv_bfloat16* pl) {
    __nv_bfloat16 h0 = __float2bfloat16(v.x);
    __nv_bfloat16 h1 = __float2bfloat16(v.y);
    __nv_bfloat16 h2 = __float2bfloat16(v.z);
    __nv_bfloat16 h3 = __float2bfloat16(v.w);
    __nv_bfloat16 l0 = __float2bfloat16(v.x - __bfloat162float(h0));
    __nv_bfloat16 l1 = __float2bfloat16(v.y - __bfloat162float(h1));
    __nv_bfloat16 l2 = __float2bfloat16(v.z - __bfloat162float(h2));
    __nv_bfloat16 l3 = __float2bfloat16(v.w - __bfloat162float(h3));
    uint2 uh = make_uint2(pack_bf16x2(h0, h1), pack_bf16x2(h2, h3));
    uint2 ul = make_uint2(pack_bf16x2(l0, l1), pack_bf16x2(l2, l3));
    *reinterpret_cast<uint2*>(ph) = uh;
    *reinterpret_cast<uint2*>(pl) = ul;
}

#define MMA_BF16(acc, a, b)                                                              \
    asm volatile(                                                                        \
        "mma.sync.aligned.m16n8k16.row.col.f32.bf16.bf16.f32 "                           \
        "{%0,%1,%2,%3}, {%4,%5,%6,%7}, {%8,%9}, {%0,%1,%2,%3};"                          \
        : "+f"((acc)[0]), "+f"((acc)[1]), "+f"((acc)[2]), "+f"((acc)[3])                 \
        : "r"((a)[0]), "r"((a)[1]), "r"((a)[2]), "r"((a)[3]), "r"((b)[0]), "r"((b)[1]))

// out[M,BN](fp16) = (relu?)(A[M,128] fp32) @ W[128,BN]
template <int BN, bool RELU>
__global__ __launch_bounds__(256) void gemm_tc_kernel(const float* __restrict__ A,
                                                      const float* __restrict__ W,
                                                      __half* __restrict__ out, int M) {
    constexpr int K = 128;
    constexpr int NWN = BN / 32;
    constexpr int NWM = 8 / NWN;
    constexpr int BM = NWM * 32;
    constexpr int KP = K + 8;
    constexpr int NP = BN + 8;

    extern __shared__ __nv_bfloat16 smb[];
    __nv_bfloat16* Ah = smb;
    __nv_bfloat16* Al = Ah + BM * KP;
    __nv_bfloat16* Wh = Al + BM * KP;
    __nv_bfloat16* Wl = Wh + K * NP;

    const int t = threadIdx.x;
    const int block_row = blockIdx.x * BM;

    for (int i = t * 4; i < K * BN; i += 1024) {
        const int k = i / BN, n = i % BN;
        float4 v = *reinterpret_cast<const float4*>(W + i);
        split_store4(v, Wh + k * NP + n, Wl + k * NP + n);
    }
    for (int i = t * 4; i < BM * K; i += 1024) {
        const int r = i >> 7, c = i & 127;
        const int row = block_row + r;
        float4 v = make_float4(0.f, 0.f, 0.f, 0.f);
        if (row < M) v = *reinterpret_cast<const float4*>(A + (size_t)row * K + c);
        if (RELU) {
            v.x = fmaxf(v.x, 0.f); v.y = fmaxf(v.y, 0.f);
            v.z = fmaxf(v.z, 0.f); v.w = fmaxf(v.w, 0.f);
        }
        split_store4(v, Ah + r * KP + c, Al + r * KP + c);
    }
    __syncthreads();

    const int w = t >> 5, l = t & 31;
    const int wm = w / NWN, wn = w % NWN;
    const int g = l >> 2, tq = l & 3;

    float acc[2][4][4];
#pragma unroll
    for (int mi = 0; mi < 2; mi++)
#pragma unroll
        for (int ni = 0; ni < 4; ni++)
#pragma unroll
            for (int r = 0; r < 4; r++) acc[mi][ni][r] = 0.f;

    const int a_row0 = wm * 32 + g;
    const int b_row  = l & 15;
    const int b_col  = wn * 32;

#pragma unroll
    for (int kk = 0; kk < 8; kk++) {
        const int k0 = kk * 16;
        uint32_t ah[2][4], al_[2][4];
#pragma unroll
        for (int mi = 0; mi < 2; mi++) {
            const int rb = (a_row0 + mi * 16) * KP + k0 + 2 * tq;
            ah[mi][0]  = *reinterpret_cast<const uint32_t*>(Ah + rb);
            ah[mi][1]  = *reinterpret_cast<const uint32_t*>(Ah + rb + 8 * KP);
            ah[mi][2]  = *reinterpret_cast<const uint32_t*>(Ah + rb + 8);
            ah[mi][3]  = *reinterpret_cast<const uint32_t*>(Ah + rb + 8 * KP + 8);
            al_[mi][0] = *reinterpret_cast<const uint32_t*>(Al + rb);
            al_[mi][1] = *reinterpret_cast<const uint32_t*>(Al + rb + 8 * KP);
            al_[mi][2] = *reinterpret_cast<const uint32_t*>(Al + rb + 8);
            al_[mi][3] = *reinterpret_cast<const uint32_t*>(Al + rb + 8 * KP + 8);
        }
        uint32_t bh[4][2], bl[4][2];
#pragma unroll
        for (int ni = 0; ni < 4; ni++) {
            const int off = (k0 + b_row) * NP + b_col + ni * 8;
            uint32_t ph = (uint32_t)__cvta_generic_to_shared(Wh + off);
            uint32_t pl = (uint32_t)__cvta_generic_to_shared(Wl + off);
            asm volatile("ldmatrix.sync.aligned.m8n8.x2.trans.shared.b16 {%0,%1}, [%2];"
                         : "=r"(bh[ni][0]), "=r"(bh[ni][1]) : "r"(ph));
            asm volatile("ldmatrix.sync.aligned.m8n8.x2.trans.shared.b16 {%0,%1}, [%2];"
                         : "=r"(bl[ni][0]), "=r"(bl[ni][1]) : "r"(pl));
        }
#pragma unroll
        for (int mi = 0; mi < 2; mi++)
#pragma unroll
            for (int ni = 0; ni < 4; ni++) {
                MMA_BF16(acc[mi][ni], ah[mi], bh[ni]);
                MMA_BF16(acc[mi][ni], ah[mi], bl[ni]);
                MMA_BF16(acc[mi][ni], al_[mi], bh[ni]);
            }
    }

#pragma unroll
    for (int mi = 0; mi < 2; mi++) {
#pragma unroll
        for (int ni = 0; ni < 4; ni++) {
            const int row = block_row + wm * 32 + mi * 16 + g;
            const int col = wn * 32 + ni * 8 + 2 * tq;
            if (row < M)
                *reinterpret_cast<__half2*>(out + (size_t)row * BN + col) =
                    __floats2half2_rn(acc[mi][ni][0], acc[mi][ni][1]);
            if (row + 8 < M)
                *reinterpret_cast<__half2*>(out + (size_t)(row + 8) * BN + col) =
                    __floats2half2_rn(acc[mi][ni][2], acc[mi][ni][3]);
        }
    }
}

// ---------------- aggregation: warp-per-node CSR gather (fp16 reads) --------
__device__ __forceinline__ void stcs4(float* p, float4 v) {
    asm volatile("st.global.cs.v4.f32 [%0], {%1,%2,%3,%4};"
                 :: "l"(p), "f"(v.x), "f"(v.y), "f"(v.z), "f"(v.w) : "memory");
}

__device__ __forceinline__ float4 ld_h4(const __half* p) {
    uint2 raw = *reinterpret_cast<const uint2*>(p);
    __half2 p0 = *reinterpret_cast<__half2*>(&raw.x);
    __half2 p1 = *reinterpret_cast<__half2*>(&raw.y);
    float2 f0 = __half22float2(p0);
    float2 f1 = __half22float2(p1);
    return make_float4(f0.x, f0.y, f1.x, f1.y);
}

__global__ void agg_gather128_kernel(const __half* __restrict__ h,
                                     const int* __restrict__ rowptr,
                                     const int* __restrict__ cnt,
                                     const int* __restrict__ csr_src,
                                     const float* __restrict__ csr_norm,
                                     const float* __restrict__ b,
                                     const float* __restrict__ dis,
                                     float* __restrict__ out, int n) {
    int v = (blockIdx.x * blockDim.x + threadIdx.x) >> 5;
    int lane = threadIdx.x & 31;
    if (v >= n) return;
    const int c = lane * 4;

    float d = dis[v];
    float sn = d * d;
    float4 acc = *reinterpret_cast<const float4*>(b + c);
    float4 hv = ld_h4(h + (size_t)v * 128 + c);
    acc.x += sn * hv.x; acc.y += sn * hv.y; acc.z += sn * hv.z; acc.w += sn * hv.w;

    int j = rowptr[v];
    const int end = j + cnt[v];
    for (; j + 8 <= end; j += 8) {
        int s[8]; float nn[8];
#pragma unroll
        for (int q = 0; q < 8; q++) { s[q] = __ldg(csr_src + j + q); nn[q] = __ldg(csr_norm + j + q); }
        float4 vv[8];
#pragma unroll
        for (int q = 0; q < 8; q++)
            vv[q] = ld_h4(h + (size_t)s[q] * 128 + c);
#pragma unroll
        for (int q = 0; q < 8; q++) {
            acc.x += nn[q] * vv[q].x; acc.y += nn[q] * vv[q].y;
            acc.z += nn[q] * vv[q].z; acc.w += nn[q] * vv[q].w;
        }
    }
    for (; j < end; ++j) {
        int s = __ldg(csr_src + j);
        float nn = __ldg(csr_norm + j);
        float4 vv = ld_h4(h + (size_t)s * 128 + c);
        acc.x += nn * vv.x; acc.y += nn * vv.y; acc.z += nn * vv.z; acc.w += nn * vv.w;
    }
    stcs4(out + (size_t)v * 128 + c, acc);
}

// final layer: 64-dim gather (fp16 reads) fused with relu + log_softmax
__global__ void agg_final_kernel(const __half* __restrict__ h,
                                 const int* __restrict__ rowptr,
                                 const int* __restrict__ cnt,
                                 const int* __restrict__ csr_src,
                                 const float* __restrict__ csr_norm,
                                 const float* __restrict__ b,
                                 const float* __restrict__ dis,
                                 float* __restrict__ out, int n) {
    int v = (blockIdx.x * blockDim.x + threadIdx.x) >> 5;
    int lane = threadIdx.x & 31;
    if (v >= n) return;
    const int c = lane * 2;

    float d = dis[v];
    float sn = d * d;
    float2 acc = *reinterpret_cast<const float2*>(b + c);
    float2 hv = __half22float2(*reinterpret_cast<const __half2*>(h + (size_t)v * 64 + c));
    acc.x += sn * hv.x; acc.y += sn * hv.y;

    int j = rowptr[v];
    const int end = j + cnt[v];
    for (; j + 8 <= end; j += 8) {
        int s[8]; float nn[8];
#pragma unroll
        for (int q = 0; q < 8; q++) { s[q] = __ldg(csr_src + j + q); nn[q] = __ldg(csr_norm + j + q); }
        float2 vv[8];
#pragma unroll
        for (int q = 0; q < 8; q++)
            vv[q] = __half22float2(*reinterpret_cast<const __half2*>(h + (size_t)s[q] * 64 + c));
#pragma unroll
        for (int q = 0; q < 8; q++) { acc.x += nn[q] * vv[q].x; acc.y += nn[q] * vv[q].y; }
    }
    for (; j < end; ++j) {
        int s = __ldg(csr_src + j);
        float nn = __ldg(csr_norm + j);
        float2 vv = __half22float2(*reinterpret_cast<const __half2*>(h + (size_t)s * 64 + c));
        acc.x += nn * vv.x; acc.y += nn * vv.y;
    }

    // relu + log_softmax over the 64 values held by this warp
    float r0 = fmaxf(acc.x, 0.f);
    float r1 = fmaxf(acc.y, 0.f);
    float m = fmaxf(r0, r1);
#pragma unroll
    for (int o = 16; o > 0; o >>= 1) m = fmaxf(m, __shfl_xor_sync(0xffffffffu, m, o));
    float s = __expf(r0 - m) + __expf(r1 - m);
#pragma unroll
    for (int o = 16; o > 0; o >>= 1) s += __shfl_xor_sync(0xffffffffu, s, o);
    float lg = m + __logf(s);
    *reinterpret_cast<float2*>(out + (size_t)v * 64 + c) = make_float2(r0 - lg, r1 - lg);
}

// ---------------- launch ----------------------------------------------------
extern "C" void kernel_launch(void* const* d_in, const int* in_sizes, int n_in,
                              void* d_out, int out_size) {
    const float* x  = (const float*)d_in[0];
    const int*   ei = (const int*)d_in[1];
    const float* W0 = (const float*)d_in[2];
    const float* b0 = (const float*)d_in[3];
    const float* W1 = (const float*)d_in[4];
    const float* b1 = (const float*)d_in[5];
    const float* W2 = (const float*)d_in[6];
    const float* b2 = (const float*)d_in[7];

    const int N = in_sizes[0] / FDIM;
    const int E = in_sizes[1] / 2;
    const int* src = ei;
    const int* dst = ei + E;

    __half* h;
    float *buf, *dis, *csr_norm;
    int *cnt, *rowptr, *cursor, *bsum, *csr_src;
    cudaGetSymbolAddress((void**)&h, g_h);
    cudaGetSymbolAddress((void**)&buf, g_buf);
    cudaGetSymbolAddress((void**)&dis, g_dis);
    cudaGetSymbolAddress((void**)&cnt, g_cnt);
    cudaGetSymbolAddress((void**)&rowptr, g_rowptr);
    cudaGetSymbolAddress((void**)&cursor, g_cursor);
    cudaGetSymbolAddress((void**)&bsum, g_bsum);
    cudaGetSymbolAddress((void**)&csr_src, g_csr_src);
    cudaGetSymbolAddress((void**)&csr_norm, g_csr_norm);

    const int smemTC128 = (2 * 64 * 136 + 2 * 128 * 136) * 2;   // 104448
    const int smemTC64  = (2 * 128 * 136 + 2 * 128 * 72) * 2;   // 106496
    cudaFuncSetAttribute((const void*)gemm_tc_kernel<128, false>,
                         cudaFuncAttributeMaxDynamicSharedMemorySize, smemTC128);
    cudaFuncSetAttribute((const void*)gemm_tc_kernel<128, true>,
                         cudaFuncAttributeMaxDynamicSharedMemorySize, smemTC128);
    cudaFuncSetAttribute((const void*)gemm_tc_kernel<64, true>,
                         cudaFuncAttributeMaxDynamicSharedMemorySize, smemTC64);

    // side stream + events, created once on the (uncaptured) correctness call
    static cudaStream_t s2 = nullptr;
    static cudaEvent_t evFork = nullptr, evJoin = nullptr;
    if (s2 == nullptr) {
        cudaStreamCreate(&s2);
        cudaEventCreateWithFlags(&evFork, cudaEventDisableTiming);
        cudaEventCreateWithFlags(&evJoin, cudaEventDisableTiming);
    }

    const int T = 256;
    auto cdiv = [](long long a, long long b) { return (unsigned)((a + b - 1) / b); };
    const int nb = (int)cdiv(N, SCAN_B);

    // ---- fork: CSR build on s2, GEMM-0 on main stream ----
    cudaEventRecord(evFork, 0);
    cudaStreamWaitEvent(s2, evFork, 0);

    zero_cnt_kernel<<<cdiv(N, T), T, 0, s2>>>(cnt, N);
    hist_kernel<<<cdiv(E, T), T, 0, s2>>>(dst, cnt, E);
    dis_kernel<<<cdiv(N, T), T, 0, s2>>>(cnt, dis, N);
    scan1_kernel<<<nb, SCAN_B, 0, s2>>>(cnt, rowptr, bsum, N);
    scan2_kernel<<<1, SCAN_B, 0, s2>>>(bsum, nb);
    scan3_kernel<<<cdiv(N, T), T, 0, s2>>>(rowptr, cursor, bsum, N);
    permute_kernel<<<cdiv(E, T), T, 0, s2>>>(src, dst, dis, cursor, csr_src, csr_norm, E);
    cudaEventRecord(evJoin, s2);

    gemm_tc_kernel<128, false><<<cdiv(N, 64), T, smemTC128>>>(x, W0, h, N);

    cudaStreamWaitEvent(0, evJoin, 0);  // gathers need CSR

    const unsigned warp_grid = cdiv((long long)N * 32, T);

    // layer 0
    agg_gather128_kernel<<<warp_grid, T>>>(h, rowptr, cnt, csr_src, csr_norm, b0, dis, buf, N);

    // layer 1
    gemm_tc_kernel<128, true><<<cdiv(N, 64), T, smemTC128>>>(buf, W1, h, N);
    agg_gather128_kernel<<<warp_grid, T>>>(h, rowptr, cnt, csr_src, csr_norm, b1, dis, buf, N);

    // layer 2 (64 out dims, BM=128), h used with stride 64
    gemm_tc_kernel<64, true><<<cdiv(N, 128), T, smemTC64>>>(buf, W2, h, N);

    // final: 64-dim gather + relu + log_softmax fused -> d_out
    agg_final_kernel<<<warp_grid, T>>>(h, rowptr, cnt, csr_src, csr_norm, b2, dis, (float*)d_out, N);
}

// round 14
// speedup vs baseline: 1.7577x; 1.4733x over previous
#include <cuda_runtime.h>
#include <cuda_bf16.h>
#include <cuda_fp16.h>
#include <cstdint>

#define N_NODES_MAX 100000
#define E_MAX       1600000
#define FDIM        128
#define SCAN_B      1024

// ---------------- scratch (device globals; no allocations allowed) ----------
__device__ __half g_h[N_NODES_MAX * FDIM];   // GEMM output, fp16 (25.6 MB)
__device__ __half g_buf[N_NODES_MAX * FDIM]; // gather output, fp16 (25.6 MB)
__device__ float  g_dis[N_NODES_MAX];
__device__ int    g_cnt[N_NODES_MAX];
__device__ int    g_rowptr[N_NODES_MAX];
__device__ int    g_cursor[N_NODES_MAX];
__device__ int    g_bsum[(N_NODES_MAX + SCAN_B - 1) / SCAN_B + 1];
__device__ int    g_csr_src[E_MAX];
__device__ float  g_csr_norm[E_MAX];

// ---------------- CSR build --------------------------------------------------
__global__ void zero_cnt_kernel(int* cnt, int n) {
    int i = blockIdx.x * blockDim.x + threadIdx.x;
    if (i < n) cnt[i] = 0;
}

__global__ void hist_kernel(const int* __restrict__ dst, int* cnt, int E) {
    int e = blockIdx.x * blockDim.x + threadIdx.x;
    if (e < E) atomicAdd(&cnt[dst[e]], 1);
}

__global__ void dis_kernel(const int* __restrict__ cnt, float* dis, int n) {
    int i = blockIdx.x * blockDim.x + threadIdx.x;
    if (i < n) dis[i] = rsqrtf((float)(cnt[i] + 1));
}

__global__ void scan1_kernel(const int* __restrict__ cnt, int* rowptr, int* bsum, int n) {
    __shared__ int sh[SCAN_B];
    int gid = blockIdx.x * SCAN_B + threadIdx.x;
    int v = (gid < n) ? cnt[gid] : 0;
    sh[threadIdx.x] = v;
    __syncthreads();
#pragma unroll
    for (int off = 1; off < SCAN_B; off <<= 1) {
        int t = (threadIdx.x >= off) ? sh[threadIdx.x - off] : 0;
        __syncthreads();
        sh[threadIdx.x] += t;
        __syncthreads();
    }
    if (gid < n) rowptr[gid] = sh[threadIdx.x] - v;
    if (threadIdx.x == SCAN_B - 1) bsum[blockIdx.x] = sh[SCAN_B - 1];
}

__global__ void scan2_kernel(int* bsum, int nb) {
    __shared__ int sh[SCAN_B];
    int v = (threadIdx.x < nb) ? bsum[threadIdx.x] : 0;
    sh[threadIdx.x] = v;
    __syncthreads();
#pragma unroll
    for (int off = 1; off < SCAN_B; off <<= 1) {
        int t = (threadIdx.x >= off) ? sh[threadIdx.x - off] : 0;
        __syncthreads();
        sh[threadIdx.x] += t;
        __syncthreads();
    }
    if (threadIdx.x < nb) bsum[threadIdx.x] = sh[threadIdx.x] - v;
}

__global__ void scan3_kernel(int* rowptr, int* cursor, const int* __restrict__ bsum, int n) {
    int gid = blockIdx.x * blockDim.x + threadIdx.x;
    if (gid < n) {
        int r = rowptr[gid] + bsum[gid / SCAN_B];
        rowptr[gid] = r;
        cursor[gid] = r;
    }
}

__global__ void permute_kernel(const int* __restrict__ src, const int* __restrict__ dst,
                               const float* __restrict__ dis, int* cursor,
                               int* csr_src, float* csr_norm, int E) {
    int e = blockIdx.x * blockDim.x + threadIdx.x;
    if (e < E) {
        int s = src[e], d = dst[e];
        int pos = atomicAdd(&cursor[d], 1);
        csr_src[pos] = s;
        csr_norm[pos] = dis[s] * dis[d];
    }
}

// ---------------- tensor-core GEMM (pure bf16, mma.sync), fp16 output -------
__device__ __forceinline__ uint32_t pack_bf16x2(__nv_bfloat16 e0, __nv_bfloat16 e1) {
    return ((uint32_t)__bfloat16_as_ushort(e1) << 16) | (uint32_t)__bfloat16_as_ushort(e0);
}

#define MMA_BF16(acc, a, b)                                                              \
    asm volatile(                                                                        \
        "mma.sync.aligned.m16n8k16.row.col.f32.bf16.bf16.f32 "                           \
        "{%0,%1,%2,%3}, {%4,%5,%6,%7}, {%8,%9}, {%0,%1,%2,%3};"                          \
        : "+f"((acc)[0]), "+f"((acc)[1]), "+f"((acc)[2]), "+f"((acc)[3])                 \
        : "r"((a)[0]), "r"((a)[1]), "r"((a)[2]), "r"((a)[3]), "r"((b)[0]), "r"((b)[1]))

// shared mainloop body (A/W already staged in smem as bf16)
template <int BN>
__device__ __forceinline__ void gemm_mainloop(const __nv_bfloat16* Ah,
                                              const __nv_bfloat16* Wh,
                                              __half* __restrict__ out,
                                              int block_row, int M) {
    constexpr int K = 128;
    constexpr int NWN = BN / 32;
    constexpr int KP = K + 8;
    constexpr int NP = BN + 8;

    const int t = threadIdx.x;
    const int w = t >> 5, l = t & 31;
    const int wm = w / NWN, wn = w % NWN;
    const int g = l >> 2, tq = l & 3;

    float acc[2][4][4];
#pragma unroll
    for (int mi = 0; mi < 2; mi++)
#pragma unroll
        for (int ni = 0; ni < 4; ni++)
#pragma unroll
            for (int r = 0; r < 4; r++) acc[mi][ni][r] = 0.f;

    const int a_row0 = wm * 32 + g;
    const int b_row  = l & 15;
    const int b_col  = wn * 32;

#pragma unroll
    for (int kk = 0; kk < 8; kk++) {
        const int k0 = kk * 16;
        uint32_t ah[2][4];
#pragma unroll
        for (int mi = 0; mi < 2; mi++) {
            const int rb = (a_row0 + mi * 16) * KP + k0 + 2 * tq;
            ah[mi][0] = *reinterpret_cast<const uint32_t*>(Ah + rb);
            ah[mi][1] = *reinterpret_cast<const uint32_t*>(Ah + rb + 8 * KP);
            ah[mi][2] = *reinterpret_cast<const uint32_t*>(Ah + rb + 8);
            ah[mi][3] = *reinterpret_cast<const uint32_t*>(Ah + rb + 8 * KP + 8);
        }
        uint32_t bh[4][2];
#pragma unroll
        for (int ni = 0; ni < 4; ni++) {
            const int off = (k0 + b_row) * NP + b_col + ni * 8;
            uint32_t ph = (uint32_t)__cvta_generic_to_shared(Wh + off);
            asm volatile("ldmatrix.sync.aligned.m8n8.x2.trans.shared.b16 {%0,%1}, [%2];"
                         : "=r"(bh[ni][0]), "=r"(bh[ni][1]) : "r"(ph));
        }
#pragma unroll
        for (int mi = 0; mi < 2; mi++)
#pragma unroll
            for (int ni = 0; ni < 4; ni++)
                MMA_BF16(acc[mi][ni], ah[mi], bh[ni]);
    }

#pragma unroll
    for (int mi = 0; mi < 2; mi++) {
#pragma unroll
        for (int ni = 0; ni < 4; ni++) {
            const int row = block_row + wm * 32 + mi * 16 + g;
            const int col = wn * 32 + ni * 8 + 2 * tq;
            if (row < M)
                *reinterpret_cast<__half2*>(out + (size_t)row * BN + col) =
                    __floats2half2_rn(acc[mi][ni][0], acc[mi][ni][1]);
            if (row + 8 < M)
                *reinterpret_cast<__half2*>(out + (size_t)(row + 8) * BN + col) =
                    __floats2half2_rn(acc[mi][ni][2], acc[mi][ni][3]);
        }
    }
}

// stage W hi-only (fp32 -> bf16)
template <int BN>
__device__ __forceinline__ void stage_W(const float* __restrict__ W, __nv_bfloat16* Wh) {
    constexpr int K = 128, NP = BN + 8;
    const int t = threadIdx.x;
    for (int i = t * 4; i < K * BN; i += 1024) {
        const int k = i / BN, n = i % BN;
        float4 v = *reinterpret_cast<const float4*>(W + i);
        uint2 u = make_uint2(pack_bf16x2(__float2bfloat16(v.x), __float2bfloat16(v.y)),
                             pack_bf16x2(__float2bfloat16(v.z), __float2bfloat16(v.w)));
        *reinterpret_cast<uint2*>(Wh + k * NP + n) = u;
    }
}

// GEMM with fp32 input A (layer 0 only, no relu)
__global__ __launch_bounds__(256) void gemm_f32in_kernel(const float* __restrict__ A,
                                                         const float* __restrict__ W,
                                                         __half* __restrict__ out, int M) {
    constexpr int BN = 128, K = 128, BM = 64, KP = K + 8, NP = BN + 8;
    extern __shared__ __nv_bfloat16 smb[];
    __nv_bfloat16* Ah = smb;              // [BM][KP]
    __nv_bfloat16* Wh = Ah + BM * KP;     // [K][NP]

    const int t = threadIdx.x;
    const int block_row = blockIdx.x * BM;

    stage_W<BN>(W, Wh);
    for (int i = t * 4; i < BM * K; i += 1024) {
        const int r = i >> 7, c = i & 127;
        const int row = block_row + r;
        float4 v = make_float4(0.f, 0.f, 0.f, 0.f);
        if (row < M) v = *reinterpret_cast<const float4*>(A + (size_t)row * K + c);
        uint2 u = make_uint2(pack_bf16x2(__float2bfloat16(v.x), __float2bfloat16(v.y)),
                             pack_bf16x2(__float2bfloat16(v.z), __float2bfloat16(v.w)));
        *reinterpret_cast<uint2*>(Ah + r * KP + c) = u;
    }
    __syncthreads();
    gemm_mainloop<BN>(Ah, Wh, out, block_row, M);
}

// GEMM with fp16 input A (+relu fused)
template <int BN>
__global__ __launch_bounds__(256) void gemm_f16in_kernel(const __half* __restrict__ A,
                                                         const float* __restrict__ W,
                                                         __half* __restrict__ out, int M) {
    constexpr int K = 128;
    constexpr int NWN = BN / 32;
    constexpr int BM = (8 / NWN) * 32;   // 64 or 128
    constexpr int KP = K + 8, NP = BN + 8;
    extern __shared__ __nv_bfloat16 smb[];
    __nv_bfloat16* Ah = smb;              // [BM][KP]
    __nv_bfloat16* Wh = Ah + BM * KP;     // [K][NP]

    const int t = threadIdx.x;
    const int block_row = blockIdx.x * BM;

    stage_W<BN>(W, Wh);
    for (int i = t * 8; i < BM * K; i += 2048) {
        const int r = i >> 7, c = i & 127;
        const int row = block_row + r;
        uint4 raw = make_uint4(0u, 0u, 0u, 0u);
        if (row < M) raw = *reinterpret_cast<const uint4*>(A + (size_t)row * K + c);
        const __half2* hp = reinterpret_cast<const __half2*>(&raw);
        uint32_t u[4];
#pragma unroll
        for (int q = 0; q < 4; q++) {
            float2 f = __half22float2(hp[q]);
            f.x = fmaxf(f.x, 0.f);
            f.y = fmaxf(f.y, 0.f);
            u[q] = pack_bf16x2(__float2bfloat16(f.x), __float2bfloat16(f.y));
        }
        *reinterpret_cast<uint4*>(Ah + r * KP + c) = make_uint4(u[0], u[1], u[2], u[3]);
    }
    __syncthreads();
    gemm_mainloop<BN>(Ah, Wh, out, block_row, M);
}

// ---------------- aggregation: warp-per-node CSR gather (fp16 in/out) -------
__device__ __forceinline__ float4 ld_h4(const __half* p) {
    uint2 raw = *reinterpret_cast<const uint2*>(p);
    __half2 p0 = *reinterpret_cast<__half2*>(&raw.x);
    __half2 p1 = *reinterpret_cast<__half2*>(&raw.y);
    float2 f0 = __half22float2(p0);
    float2 f1 = __half22float2(p1);
    return make_float4(f0.x, f0.y, f1.x, f1.y);
}

__device__ __forceinline__ void stcs_h4(__half* p, float4 v) {
    __half2 a = __floats2half2_rn(v.x, v.y);
    __half2 b = __floats2half2_rn(v.z, v.w);
    uint32_t ua = *reinterpret_cast<uint32_t*>(&a);
    uint32_t ub = *reinterpret_cast<uint32_t*>(&b);
    asm volatile("st.global.cs.v2.b32 [%0], {%1,%2};"
                 :: "l"(p), "r"(ua), "r"(ub) : "memory");
}

__global__ void agg_gather128_kernel(const __half* __restrict__ h,
                                     const int* __restrict__ rowptr,
                                     const int* __restrict__ cnt,
                                     const int* __restrict__ csr_src,
                                     const float* __restrict__ csr_norm,
                                     const float* __restrict__ b,
                                     const float* __restrict__ dis,
                                     __half* __restrict__ out, int n) {
    int v = (blockIdx.x * blockDim.x + threadIdx.x) >> 5;
    int lane = threadIdx.x & 31;
    if (v >= n) return;
    const int c = lane * 4;

    float d = dis[v];
    float sn = d * d;
    float4 acc = *reinterpret_cast<const float4*>(b + c);
    float4 hv = ld_h4(h + (size_t)v * 128 + c);
    acc.x += sn * hv.x; acc.y += sn * hv.y; acc.z += sn * hv.z; acc.w += sn * hv.w;

    int j = rowptr[v];
    const int end = j + cnt[v];
    for (; j + 8 <= end; j += 8) {
        int s[8]; float nn[8];
#pragma unroll
        for (int q = 0; q < 8; q++) { s[q] = __ldg(csr_src + j + q); nn[q] = __ldg(csr_norm + j + q); }
        float4 vv[8];
#pragma unroll
        for (int q = 0; q < 8; q++)
            vv[q] = ld_h4(h + (size_t)s[q] * 128 + c);
#pragma unroll
        for (int q = 0; q < 8; q++) {
            acc.x += nn[q] * vv[q].x; acc.y += nn[q] * vv[q].y;
            acc.z += nn[q] * vv[q].z; acc.w += nn[q] * vv[q].w;
        }
    }
    for (; j < end; ++j) {
        int s = __ldg(csr_src + j);
        float nn = __ldg(csr_norm + j);
        float4 vv = ld_h4(h + (size_t)s * 128 + c);
        acc.x += nn * vv.x; acc.y += nn * vv.y; acc.z += nn * vv.z; acc.w += nn * vv.w;
    }
    stcs_h4(out + (size_t)v * 128 + c, acc);
}

// final layer: 64-dim gather (fp16 reads) fused with relu + log_softmax
__global__ void agg_final_kernel(const __half* __restrict__ h,
                                 const int* __restrict__ rowptr,
                                 const int* __restrict__ cnt,
                                 const int* __restrict__ csr_src,
                                 const float* __restrict__ csr_norm,
                                 const float* __restrict__ b,
                                 const float* __restrict__ dis,
                                 float* __restrict__ out, int n) {
    int v = (blockIdx.x * blockDim.x + threadIdx.x) >> 5;
    int lane = threadIdx.x & 31;
    if (v >= n) return;
    const int c = lane * 2;

    float d = dis[v];
    float sn = d * d;
    float2 acc = *reinterpret_cast<const float2*>(b + c);
    float2 hv = __half22float2(*reinterpret_cast<const __half2*>(h + (size_t)v * 64 + c));
    acc.x += sn * hv.x; acc.y += sn * hv.y;

    int j = rowptr[v];
    const int end = j + cnt[v];
    for (; j + 8 <= end; j += 8) {
        int s[8]; float nn[8];
#pragma unroll
        for (int q = 0; q < 8; q++) { s[q] = __ldg(csr_src + j + q); nn[q] = __ldg(csr_norm + j + q); }
        float2 vv[8];
#pragma unroll
        for (int q = 0; q < 8; q++)
            vv[q] = __half22float2(*reinterpret_cast<const __half2*>(h + (size_t)s[q] * 64 + c));
#pragma unroll
        for (int q = 0; q < 8; q++) { acc.x += nn[q] * vv[q].x; acc.y += nn[q] * vv[q].y; }
    }
    for (; j < end; ++j) {
        int s = __ldg(csr_src + j);
        float nn = __ldg(csr_norm + j);
        float2 vv = __half22float2(*reinterpret_cast<const __half2*>(h + (size_t)s * 64 + c));
        acc.x += nn * vv.x; acc.y += nn * vv.y;
    }

    float r0 = fmaxf(acc.x, 0.f);
    float r1 = fmaxf(acc.y, 0.f);
    float m = fmaxf(r0, r1);
#pragma unroll
    for (int o = 16; o > 0; o >>= 1) m = fmaxf(m, __shfl_xor_sync(0xffffffffu, m, o));
    float s = __expf(r0 - m) + __expf(r1 - m);
#pragma unroll
    for (int o = 16; o > 0; o >>= 1) s += __shfl_xor_sync(0xffffffffu, s, o);
    float lg = m + __logf(s);
    *reinterpret_cast<float2*>(out + (size_t)v * 64 + c) = make_float2(r0 - lg, r1 - lg);
}

// ---------------- launch ----------------------------------------------------
extern "C" void kernel_launch(void* const* d_in, const int* in_sizes, int n_in,
                              void* d_out, int out_size) {
    const float* x  = (const float*)d_in[0];
    const int*   ei = (const int*)d_in[1];
    const float* W0 = (const float*)d_in[2];
    const float* b0 = (const float*)d_in[3];
    const float* W1 = (const float*)d_in[4];
    const float* b1 = (const float*)d_in[5];
    const float* W2 = (const float*)d_in[6];
    const float* b2 = (const float*)d_in[7];

    const int N = in_sizes[0] / FDIM;
    const int E = in_sizes[1] / 2;
    const int* src = ei;
    const int* dst = ei + E;

    __half *h, *buf;
    float *dis, *csr_norm;
    int *cnt, *rowptr, *cursor, *bsum, *csr_src;
    cudaGetSymbolAddress((void**)&h, g_h);
    cudaGetSymbolAddress((void**)&buf, g_buf);
    cudaGetSymbolAddress((void**)&dis, g_dis);
    cudaGetSymbolAddress((void**)&cnt, g_cnt);
    cudaGetSymbolAddress((void**)&rowptr, g_rowptr);
    cudaGetSymbolAddress((void**)&cursor, g_cursor);
    cudaGetSymbolAddress((void**)&bsum, g_bsum);
    cudaGetSymbolAddress((void**)&csr_src, g_csr_src);
    cudaGetSymbolAddress((void**)&csr_norm, g_csr_norm);

    // smem: (BM*136 + 128*(BN+8)) bf16 elements * 2B
    const int smem128 = (64 * 136 + 128 * 136) * 2;   // 52224
    const int smem64  = (128 * 136 + 128 * 72) * 2;   // 53248
    cudaFuncSetAttribute((const void*)gemm_f32in_kernel,
                         cudaFuncAttributeMaxDynamicSharedMemorySize, smem128);
    cudaFuncSetAttribute((const void*)gemm_f16in_kernel<128>,
                         cudaFuncAttributeMaxDynamicSharedMemorySize, smem128);
    cudaFuncSetAttribute((const void*)gemm_f16in_kernel<64>,
                         cudaFuncAttributeMaxDynamicSharedMemorySize, smem64);

    // side stream + events, created once on the (uncaptured) correctness call
    static cudaStream_t s2 = nullptr;
    static cudaEvent_t evFork = nullptr, evJoin = nullptr;
    if (s2 == nullptr) {
        cudaStreamCreate(&s2);
        cudaEventCreateWithFlags(&evFork, cudaEventDisableTiming);
        cudaEventCreateWithFlags(&evJoin, cudaEventDisableTiming);
    }

    const int T = 256;
    auto cdiv = [](long long a, long long b) { return (unsigned)((a + b - 1) / b); };
    const int nb = (int)cdiv(N, SCAN_B);

    // ---- fork: CSR build on s2, GEMM-0 on main stream ----
    cudaEventRecord(evFork, 0);
    cudaStreamWaitEvent(s2, evFork, 0);

    zero_cnt_kernel<<<cdiv(N, T), T, 0, s2>>>(cnt, N);
    hist_kernel<<<cdiv(E, T), T, 0, s2>>>(dst, cnt, E);
    dis_kernel<<<cdiv(N, T), T, 0, s2>>>(cnt, dis, N);
    scan1_kernel<<<nb, SCAN_B, 0, s2>>>(cnt, rowptr, bsum, N);
    scan2_kernel<<<1, SCAN_B, 0, s2>>>(bsum, nb);
    scan3_kernel<<<cdiv(N, T), T, 0, s2>>>(rowptr, cursor, bsum, N);
    permute_kernel<<<cdiv(E, T), T, 0, s2>>>(src, dst, dis, cursor, csr_src, csr_norm, E);
    cudaEventRecord(evJoin, s2);

    gemm_f32in_kernel<<<cdiv(N, 64), T, smem128>>>(x, W0, h, N);

    cudaStreamWaitEvent(0, evJoin, 0);  // gathers need CSR

    const unsigned warp_grid = cdiv((long long)N * 32, T);

    // layer 0
    agg_gather128_kernel<<<warp_grid, T>>>(h, rowptr, cnt, csr_src, csr_norm, b0, dis, buf, N);

    // layer 1 (relu fused into GEMM A-stage)
    gemm_f16in_kernel<128><<<cdiv(N, 64), T, smem128>>>(buf, W1, h, N);
    agg_gather128_kernel<<<warp_grid, T>>>(h, rowptr, cnt, csr_src, csr_norm, b1, dis, buf, N);

    // layer 2 (64 out dims, BM=128)
    gemm_f16in_kernel<64><<<cdiv(N, 128), T, smem64>>>(buf, W2, h, N);

    // final: 64-dim gather + relu + log_softmax fused -> d_out
    agg_final_kernel<<<warp_grid, T>>>(h, rowptr, cnt, csr_src, csr_norm, b2, dis, (float*)d_out, N);
}